// round 11
// baseline (speedup 1.0000x reference)
#include <cuda_runtime.h>
#include <math.h>

#define BATCH 8192
#define W 256
#define KCHUNK 128
#define NKCH  (BATCH / KCHUNK)       // 64
#define NPAIR 10
#define NCB   64
#define ROWS_PER_CB (BATCH / NCB)    // 128

// Device scratch (no allocations allowed).
__device__ float g_G[W * W];          // Gram accumulator
__device__ float g_colsum[NCB][W];    // partial column sums
__device__ float g_mu[W];             // column means
__device__ float g_sumsq;             // scalar accumulator for ||D||^2
__device__ int   g_fin_count = 0;     // finalize completion counter (self-resetting)

// Upper-triangular 64x64 tile-pair enumeration: (ti, tj) with ti <= tj.
__constant__ int c_ti[NPAIR] = {0,0,0,0,1,1,1,2,2,3};
__constant__ int c_tj[NPAIR] = {0,1,2,3,1,2,3,2,3,3};

// ---- f32x2 packed-FMA helpers --------------------------------------------
__device__ __forceinline__ unsigned long long pack_f32(float lo, float hi) {
    unsigned long long r;
    asm("mov.b64 %0, {%1, %2};" : "=l"(r) : "f"(lo), "f"(hi));
    return r;
}
__device__ __forceinline__ void fma2(unsigned long long &acc,
                                     unsigned long long a, unsigned long long b) {
    asm("fma.rn.f32x2 %0, %1, %2, %0;" : "+l"(acc) : "l"(a), "l"(b));
}
__device__ __forceinline__ float2 unpack_f32x2(unsigned long long v) {
    float lo, hi;
    asm("mov.b64 {%0, %1}, %2;" : "=f"(lo), "=f"(hi) : "l"(v));
    return make_float2(lo, hi);
}

// ---------------------------------------------------------------------------
// K1: partial column sums + zero G + zero sumsq. 64 blocks x 256 threads.
// ---------------------------------------------------------------------------
__global__ void colsum_kernel(const float* __restrict__ E) {
    const int t = threadIdx.x;
    const int b = blockIdx.x;
    const int gid = b * 256 + t;

    // Zero the Gram accumulator (graph replays; must re-zero every launch).
    ((float4*)g_G)[gid] = make_float4(0.f, 0.f, 0.f, 0.f);
    if (gid == 0) g_sumsq = 0.0f;

    // Column partial sums, coalesced, 4 independent accumulators for MLP.
    const float* p = E + (size_t)b * ROWS_PER_CB * W + t;
    float s0 = 0.f, s1 = 0.f, s2 = 0.f, s3 = 0.f;
    #pragma unroll 8
    for (int r = 0; r < ROWS_PER_CB; r += 4) {
        s0 += p[(size_t)(r + 0) * W];
        s1 += p[(size_t)(r + 1) * W];
        s2 += p[(size_t)(r + 2) * W];
        s3 += p[(size_t)(r + 3) * W];
    }
    g_colsum[b][t] = (s0 + s1) + (s2 + s3);
}

// ---------------------------------------------------------------------------
// K2: Gram, symmetric tiles, diagonal-pair FFMA2. 641 blocks x 128 threads.
// Block bid < 640: pair = bid/64, chunk = bid%64, 64x64 tile, 8x4 micro-tile.
// Block bid == 640: computes g_mu from g_colsum (off the critical path).
// ---------------------------------------------------------------------------
__global__ void gram_kernel(const float* __restrict__ E) {
    const int bid = blockIdx.x;
    const int tid = threadIdx.x;

    if (bid == NPAIR * NKCH) {
        // mu block: 128 threads, 2 columns each.
        #pragma unroll
        for (int h = 0; h < 2; ++h) {
            int c = tid + h * 128;
            float s = 0.0f;
            #pragma unroll 8
            for (int b = 0; b < NCB; ++b) s += g_colsum[b][c];
            g_mu[c] = s * (1.0f / BATCH);
        }
        return;
    }

    __shared__ float As[32][64];
    __shared__ float Bs[32][64];

    const int pair  = bid / NKCH;
    const int chunk = bid % NKCH;
    const int tx  = tid & 7;          // 8 i-groups of 8 rows
    const int ty  = tid >> 3;         // 16 j-groups of 4 cols
    const int i0  = c_ti[pair] * 64;
    const int j0  = c_tj[pair] * 64;
    const int k0  = chunk * KCHUNK;

    // accA[p][q] = {G[ib+2p, jb+2q],   G[ib+2p+1, jb+2q+1]}
    // accB[p][q] = {G[ib+2p, jb+2q+1], G[ib+2p+1, jb+2q]}
    unsigned long long accA[4][2], accB[4][2];
    #pragma unroll
    for (int p = 0; p < 4; ++p)
        #pragma unroll
        for (int q = 0; q < 2; ++q) { accA[p][q] = 0ull; accB[p][q] = 0ull; }

    for (int kc = 0; kc < KCHUNK; kc += 32) {
        // Stage 32 rows x 64 cols of both operand column blocks.
        #pragma unroll
        for (int qq = 0; qq < 4; ++qq) {
            int idx = qq * 128 + tid;     // 0..511
            int row = idx >> 4;
            int f   = idx & 15;
            size_t base = (size_t)(k0 + kc + row) * W;
            ((float4*)As[row])[f] = ((const float4*)(E + base + i0))[f];
            ((float4*)Bs[row])[f] = ((const float4*)(E + base + j0))[f];
        }
        __syncthreads();

        #pragma unroll
        for (int kk = 0; kk < 32; ++kk) {
            // a: 8 floats as 2x ulonglong2 -> 4 ready-made f32x2 pairs (no MOVs)
            ulonglong2 A0 = *(const ulonglong2*)&As[kk][tx * 8];
            ulonglong2 A1 = *(const ulonglong2*)&As[kk][tx * 8 + 4];
            float4 b = *(const float4*)&Bs[kk][ty * 4];
            unsigned long long b01 = pack_f32(b.x, b.y);   // reg-coalesced
            unsigned long long b10 = pack_f32(b.y, b.x);   // swapped (2 MOV)
            unsigned long long b23 = pack_f32(b.z, b.w);
            unsigned long long b32 = pack_f32(b.w, b.z);

            fma2(accA[0][0], A0.x, b01);  fma2(accB[0][0], A0.x, b10);
            fma2(accA[0][1], A0.x, b23);  fma2(accB[0][1], A0.x, b32);
            fma2(accA[1][0], A0.y, b01);  fma2(accB[1][0], A0.y, b10);
            fma2(accA[1][1], A0.y, b23);  fma2(accB[1][1], A0.y, b32);
            fma2(accA[2][0], A1.x, b01);  fma2(accB[2][0], A1.x, b10);
            fma2(accA[2][1], A1.x, b23);  fma2(accB[2][1], A1.x, b32);
            fma2(accA[3][0], A1.y, b01);  fma2(accB[3][0], A1.y, b10);
            fma2(accA[3][1], A1.y, b23);  fma2(accB[3][1], A1.y, b32);
        }
        __syncthreads();
    }

    const int ib = i0 + tx * 8;
    const int jb = j0 + ty * 4;
    #pragma unroll
    for (int p = 0; p < 4; ++p) {
        #pragma unroll
        for (int q = 0; q < 2; ++q) {
            float2 va = unpack_f32x2(accA[p][q]);
            float2 vb = unpack_f32x2(accB[p][q]);
            int gi = ib + 2 * p;
            int gj = jb + 2 * q;
            atomicAdd(&g_G[gi * W + gj],           va.x);
            atomicAdd(&g_G[gi * W + gj + 1],       vb.x);
            atomicAdd(&g_G[(gi + 1) * W + gj],     vb.y);
            atomicAdd(&g_G[(gi + 1) * W + gj + 1], va.y);
        }
    }
}

// ---------------------------------------------------------------------------
// K3: finalize. 128 blocks x 256 threads; block b -> rows b and 255-b.
// Last block to finish computes sqrt and writes the output scalar.
// ---------------------------------------------------------------------------
__global__ void finalize_kernel(float* __restrict__ out) {
    __shared__ float mu[W];
    __shared__ float red[256];

    const int t = threadIdx.x;
    mu[t] = g_mu[t];
    __syncthreads();

    const float invB = 1.0f / BATCH;
    float acc = 0.0f;
    int rows[2] = {(int)blockIdx.x, (W - 1) - (int)blockIdx.x};
    #pragma unroll
    for (int r = 0; r < 2; ++r) {
        int i = rows[r];
        int j = i + t;                 // upper triangle only
        if (j < W) {
            float d = g_G[i * W + j] * invB - mu[i] * mu[j] - (j == i ? 1.0f : 0.0f);
            acc += (j == i ? 1.0f : 2.0f) * d * d;
        }
    }

    red[t] = acc;
    __syncthreads();
    #pragma unroll
    for (int st = 128; st > 0; st >>= 1) {
        if (t < st) red[t] += red[t + st];
        __syncthreads();
    }

    if (t == 0) {
        atomicAdd(&g_sumsq, red[0]);
        __threadfence();
        int c = atomicAdd(&g_fin_count, 1);
        if (c == 127) {
            float total = atomicAdd(&g_sumsq, 0.0f);  // coherent read
            out[0] = sqrtf(total);
            g_fin_count = 0;                          // reset for next replay
        }
    }
}

// ---------------------------------------------------------------------------
extern "C" void kernel_launch(void* const* d_in, const int* in_sizes, int n_in,
                              void* d_out, int out_size) {
    const float* E = (const float*)d_in[0];   // [8192, 256] fp32
    float* out = (float*)d_out;

    colsum_kernel<<<NCB, 256>>>(E);
    gram_kernel<<<NPAIR * NKCH + 1, 128>>>(E);
    finalize_kernel<<<W / 2, 256>>>(out);
}